// round 15
// baseline (speedup 1.0000x reference)
#include <cuda_runtime.h>
#include <cstdint>
#include <cstddef>

#define B_   8
#define N_   8192
#define S_   2048
#define K_   32
#define F_   64
#define CIN_ 67
#define EPSF 1e-5f

#define CH   10          // tapered pipeline chunks
#define FTH  256         // FPS threads per CTA
#define NP   16          // packed pairs per thread (32 points)

typedef unsigned long long ull;

// scratch
__device__ int   g_gidx[B_ * S_ * K_];
__device__ float g_mind[B_][N_];

// ---- packed f32x2 helpers (per-lane IEEE rn, bit-identical to scalar) ----
__device__ __forceinline__ ull pk2(float lo, float hi) {
    ull r; asm("mov.b64 %0, {%1, %2};" : "=l"(r) : "f"(lo), "f"(hi)); return r;
}
__device__ __forceinline__ void upk2(ull v, float& lo, float& hi) {
    asm("mov.b64 {%0, %1}, %2;" : "=f"(lo), "=f"(hi) : "l"(v));
}
__device__ __forceinline__ ull add2(ull a, ull b) {
    ull r; asm("add.rn.f32x2 %0, %1, %2;" : "=l"(r) : "l"(a), "l"(b)); return r;
}
__device__ __forceinline__ ull mul2(ull a, ull b) {
    ull r; asm("mul.rn.f32x2 %0, %1, %2;" : "=l"(r) : "l"(a), "l"(b)); return r;
}
__device__ __forceinline__ ull fma2(ull a, ull b, ull c) {
    ull r; asm("fma.rn.f32x2 %0, %1, %2, %3;" : "=l"(r) : "l"(a), "l"(b), "l"(c)); return r;
}

// ---------------------------------------------------------------------------
// Kernel 1: FPS chunk [s0, s1). One CTA per batch, 256 threads, 32 pts/thread
// (16 packed pairs, register-resident). Points stored in smem as float4 so
// the per-step center fetch is ONE LDS.128. mind persisted between chunks.
// Distance: per-lane rn ops in canonical order ((dx*dx+dy*dy)+dz*dz).
// One barrier per step; exact argmax tie-break (lowest index).
// ---------------------------------------------------------------------------
__global__ __launch_bounds__(FTH, 1)
void fps_kernel(const float* __restrict__ xyzs, float* __restrict__ outc,
                int s0, int s1, int first)
{
    extern __shared__ float4 spt[];     // [N_] x,y,z,-
    __shared__ ull swp[2][32];

    const int b    = blockIdx.x;
    const int tid  = threadIdx.x;
    const int lane = tid & 31;
    const int wid  = tid >> 5;          // 0..7
    const float* xyz = xyzs + (size_t)b * N_ * 3;

    // neutral keys for unused warp slots 8..31 (dist bits 0, idx ~0)
    if (tid < 32 && tid >= 8) {
        swp[0][tid] = 0xffffffffull;
        swp[1][tid] = 0xffffffffull;
    }

    ull px2[NP], py2[NP], pz2[NP];
    float mind[2 * NP];
#pragma unroll
    for (int p = 0; p < NP; p++) {
        int i0 = tid + (2 * p) * FTH;
        int i1 = tid + (2 * p + 1) * FTH;
        float X0 = xyz[i0 * 3 + 0], Y0 = xyz[i0 * 3 + 1], Z0 = xyz[i0 * 3 + 2];
        float X1 = xyz[i1 * 3 + 0], Y1 = xyz[i1 * 3 + 1], Z1 = xyz[i1 * 3 + 2];
        px2[p] = pk2(X0, X1); py2[p] = pk2(Y0, Y1); pz2[p] = pk2(Z0, Z1);
        spt[i0] = make_float4(X0, Y0, Z0, 0.0f);
        spt[i1] = make_float4(X1, Y1, Z1, 0.0f);
        if (first) {
            mind[2 * p] = 1e10f; mind[2 * p + 1] = 1e10f;
        } else {
            mind[2 * p]     = g_mind[b][i0];
            mind[2 * p + 1] = g_mind[b][i1];
        }
    }
    __syncthreads();

    float cx, cy, cz;
    if (first) {
        float4 p0 = spt[0];
        cx = p0.x; cy = p0.y; cz = p0.z;
        if (tid == 0) {
            float* o = outc + (size_t)b * S_ * 3;
            o[0] = cx; o[1] = cy; o[2] = cz;
        }
    } else {
        const float* o = outc + ((size_t)b * S_ + (s0 - 1)) * 3;
        cx = o[0]; cy = o[1]; cz = o[2];
    }

    for (int s = s0; s < s1; s++) {
        ull ncx2 = pk2(-cx, -cx), ncy2 = pk2(-cy, -cy), ncz2 = pk2(-cz, -cz);

        float bv = -1.0f;
#pragma unroll
        for (int p = 0; p < NP; p++) {
            ull dx2 = add2(px2[p], ncx2);
            ull dy2 = add2(py2[p], ncy2);
            ull dz2 = add2(pz2[p], ncz2);
            ull d2  = add2(add2(mul2(dx2, dx2), mul2(dy2, dy2)), mul2(dz2, dz2));
            float dlo, dhi; upk2(d2, dlo, dhi);
            float m0 = fminf(mind[2 * p],     dlo);
            float m1 = fminf(mind[2 * p + 1], dhi);
            mind[2 * p]     = m0;
            mind[2 * p + 1] = m1;
            bv = fmaxf(bv, fmaxf(m0, m1));
        }
        // distances >= 0 -> float order == unsigned bit order
        unsigned wmax  = __reduce_max_sync(0xffffffffu, __float_as_uint(bv));
        float    wmaxf = __uint_as_float(wmax);
        unsigned cand  = 0xffffffffu;
        if (__float_as_uint(bv) == wmax) {   // only holders scan
#pragma unroll
            for (int j = 2 * NP - 1; j >= 0; j--)
                if (mind[j] == wmaxf) cand = (unsigned)(tid + j * FTH);
        }
        cand = __reduce_min_sync(0xffffffffu, cand);
        if (lane == 0) swp[s & 1][wid] = ((ull)wmax << 32) | (ull)cand;
        __syncthreads();

        ull key = swp[s & 1][lane];
        unsigned hi = (unsigned)(key >> 32), lo = (unsigned)key;
        unsigned ghi  = __reduce_max_sync(0xffffffffu, hi);
        unsigned gidx = __reduce_min_sync(0xffffffffu, (hi == ghi) ? lo : 0xffffffffu);

        float4 cp = spt[gidx];          // one LDS.128
        cx = cp.x; cy = cp.y; cz = cp.z;
        if (tid == 0) {
            float* o = outc + ((size_t)b * S_ + s) * 3;
            o[0] = cx; o[1] = cy; o[2] = cz;
        }
    }

    // persist mind for the next chunk
#pragma unroll
    for (int p = 0; p < NP; p++) {
        g_mind[b][tid + (2 * p) * FTH]     = mind[2 * p];
        g_mind[b][tid + (2 * p + 1) * FTH] = mind[2 * p + 1];
    }
}

// ---------------------------------------------------------------------------
// Kernel 2: ball query chunk, warp-per-center ballot scan.
// grid = B_ * (size/16) blocks of 512 threads.
// ---------------------------------------------------------------------------
__global__ __launch_bounds__(512)
void ball_kernel(const float* __restrict__ xyzs, const float* __restrict__ centers,
                 int s0)
{
    extern __shared__ float4 sp[];   // [N_] : 128 KB

    const int bpb  = gridDim.x / B_;         // blocks per batch
    const int b    = blockIdx.x / bpb;
    const int soff = (blockIdx.x % bpb) * 16;
    const float* xyz = xyzs + (size_t)b * N_ * 3;

    for (int i = threadIdx.x; i < N_; i += 512) {
        float X = xyz[i * 3 + 0];
        float Y = xyz[i * 3 + 1];
        float Z = xyz[i * 3 + 2];
        float nrm = __fadd_rn(__fadd_rn(__fmul_rn(X, X), __fmul_rn(Y, Y)),
                              __fmul_rn(Z, Z));
        sp[i] = make_float4(X, Y, Z, nrm);
    }
    __syncthreads();

    const int warp = threadIdx.x >> 5;
    const int lane = threadIdx.x & 31;
    const int ci   = b * S_ + s0 + soff + warp;
    const float* c = centers + (size_t)ci * 3;
    const float cx = c[0], cy = c[1], cz = c[2];
    const float cc = __fadd_rn(__fadd_rn(__fmul_rn(cx, cx), __fmul_rn(cy, cy)),
                               __fmul_rn(cz, cz));
    const float R2 = 0.2f * 0.2f;
    const unsigned below = (1u << lane) - 1u;

    int cnt = 0;
    for (int chunk = 0; chunk < N_ / 32; chunk++) {
        int n = chunk * 32 + lane;
        float4 p = sp[n];
        float dot = __fadd_rn(__fadd_rn(__fmul_rn(cx, p.x), __fmul_rn(cy, p.y)),
                              __fmul_rn(cz, p.z));
        float d2  = __fsub_rn(__fadd_rn(cc, p.w), __fmul_rn(2.0f, dot));
        bool hit = (d2 <= R2);
        unsigned m = __ballot_sync(0xffffffffu, hit);
        int pos = cnt + __popc(m & below);
        if (hit && pos < K_) g_gidx[(size_t)ci * K_ + pos] = n;
        cnt += __popc(m);
        if (cnt >= K_) break;
    }
    for (int t = cnt + lane; t < K_; t += 32) g_gidx[(size_t)ci * K_ + t] = -1;
}

// ---------------------------------------------------------------------------
// Kernel 3: gather + 3-layer MLP (BN folded) + max over K, chunked.
// c-loop unrolled x2 (scheduling only — per-channel FMA order unchanged).
// ---------------------------------------------------------------------------
#define WPB 4
#define CPW 2
#define XS  69   // staging row stride (67 used), odd -> conflict-free

__device__ __forceinline__ void step64(ull* __restrict__ acc, float xv,
                                       const float* __restrict__ wrow)
{
    ull xv2 = pk2(xv, xv);
    const ulonglong2* wp = (const ulonglong2*)wrow;
#pragma unroll
    for (int t = 0; t < 16; t++) {
        ulonglong2 w = wp[t];
        acc[2 * t]     = fma2(xv2, w.x, acc[2 * t]);
        acc[2 * t + 1] = fma2(xv2, w.y, acc[2 * t + 1]);
    }
}

__global__ __launch_bounds__(128, 2)
void mlp_kernel(const float* __restrict__ xyzs, const float* __restrict__ feats,
                const float* __restrict__ w1, const float* __restrict__ b1,
                const float* __restrict__ g1, const float* __restrict__ bt1,
                const float* __restrict__ m1, const float* __restrict__ v1,
                const float* __restrict__ w2, const float* __restrict__ b2,
                const float* __restrict__ g2, const float* __restrict__ bt2,
                const float* __restrict__ m2, const float* __restrict__ v2,
                const float* __restrict__ w3, const float* __restrict__ b3,
                const float* __restrict__ g3, const float* __restrict__ bt3,
                const float* __restrict__ m3, const float* __restrict__ v3,
                const float* __restrict__ centers, float* __restrict__ outf,
                int s0)
{
    extern __shared__ float sm3[];
    float* sW1 = sm3;
    float* sW2 = sW1 + CIN_ * 64;
    float* sW3 = sW2 + 64 * 64;
    float* sB1 = sW3 + 64 * 128;
    float* sB2 = sB1 + 64;
    float* sB3 = sB2 + 64;
    float* sS  = sB3 + 128;
    float* sX  = sS + 256;

    const int tid = threadIdx.x;

    if (tid < 64) {
        float s = g1[tid] * rsqrtf(v1[tid] + EPSF);
        sS[tid] = s;
        sB1[tid] = (b1[tid] - m1[tid]) * s + bt1[tid];
    } else {
        int o = tid - 64;
        float s = g2[o] * rsqrtf(v2[o] + EPSF);
        sS[64 + o] = s;
        sB2[o] = (b2[o] - m2[o]) * s + bt2[o];
    }
    {
        float s = g3[tid] * rsqrtf(v3[tid] + EPSF);
        sS[128 + tid] = s;
        sB3[tid] = (b3[tid] - m3[tid]) * s + bt3[tid];
    }
    __syncthreads();

    for (int i = tid; i < CIN_ * 64; i += 128) {
        int c = i >> 6, o = i & 63;
        sW1[i] = w1[o * CIN_ + c] * sS[o];
    }
    for (int i = tid; i < 64 * 64; i += 128) {
        int c = i >> 6, o = i & 63;
        sW2[i] = w2[o * 64 + c] * sS[64 + o];
    }
    for (int i = tid; i < 64 * 128; i += 128) {
        int c = i >> 7, o = i & 127;
        sW3[i] = w3[o * 64 + c] * sS[128 + o];
    }
    __syncthreads();

    const int warp = tid >> 5;
    const int lane = tid & 31;
    float* myX = sX + tid * XS;

    const int pbb = gridDim.x / B_;               // blocks per batch
    const int b   = blockIdx.x / pbb;
    const int cb  = b * S_ + s0 + (blockIdx.x % pbb) * (WPB * CPW);

    for (int it = 0; it < CPW; it++) {
        const int ci = cb + warp * CPW + it;

        const int  ig    = g_gidx[(size_t)ci * K_ + lane];
        const bool valid = (ig >= 0);
        const int  ip    = valid ? ig : 0;
        const float* ctr = centers + (size_t)ci * 3;
        const float* p   = xyzs + ((size_t)b * N_ + ip) * 3;
        myX[0] = valid ? (p[0] - ctr[0]) : 0.0f;
        myX[1] = valid ? (p[1] - ctr[1]) : 0.0f;
        myX[2] = valid ? (p[2] - ctr[2]) : 0.0f;
        const float4* f4 = (const float4*)(feats + ((size_t)b * N_ + ip) * F_);
#pragma unroll
        for (int q = 0; q < 16; q++) {
            float4 t = f4[q];
            myX[3 + 4 * q + 0] = valid ? t.x : 0.0f;
            myX[3 + 4 * q + 1] = valid ? t.y : 0.0f;
            myX[3 + 4 * q + 2] = valid ? t.z : 0.0f;
            myX[3 + 4 * q + 3] = valid ? t.w : 0.0f;
        }

        ull acc[32];

        // ---- layer 1: 67 -> 64 ----
#pragma unroll
        for (int t = 0; t < 32; t++) acc[t] = ((const ull*)sB1)[t];
#pragma unroll 2
        for (int c = 0; c < CIN_ - 1; c++) step64(acc, myX[c], sW1 + c * 64);
        step64(acc, myX[CIN_ - 1], sW1 + (CIN_ - 1) * 64);
#pragma unroll
        for (int t = 0; t < 32; t++) {
            float lo, hi; upk2(acc[t], lo, hi);
            myX[2 * t]     = fmaxf(lo, 0.0f);
            myX[2 * t + 1] = fmaxf(hi, 0.0f);
        }

        // ---- layer 2: 64 -> 64 ----
#pragma unroll
        for (int t = 0; t < 32; t++) acc[t] = ((const ull*)sB2)[t];
#pragma unroll 2
        for (int c = 0; c < 64; c++) step64(acc, myX[c], sW2 + c * 64);
#pragma unroll
        for (int t = 0; t < 32; t++) {
            float lo, hi; upk2(acc[t], lo, hi);
            myX[2 * t]     = fmaxf(lo, 0.0f);
            myX[2 * t + 1] = fmaxf(hi, 0.0f);
        }

        // ---- layer 3: 64 -> 128 in two halves, relu, warp max over K ----
        float* op = outf + (size_t)ci * 128;
#pragma unroll 1
        for (int h = 0; h < 2; h++) {
#pragma unroll
            for (int t = 0; t < 32; t++) acc[t] = ((const ull*)(sB3 + h * 64))[t];
#pragma unroll 2
            for (int c = 0; c < 64; c++) step64(acc, myX[c], sW3 + c * 128 + h * 64);
#pragma unroll
            for (int t = 0; t < 32; t++) {
                float lo, hi; upk2(acc[t], lo, hi);
                unsigned ulo = __float_as_uint(fmaxf(lo, 0.0f)) & 0x7fffffffu;
                unsigned uhi = __float_as_uint(fmaxf(hi, 0.0f)) & 0x7fffffffu;
                float rlo = __uint_as_float(__reduce_max_sync(0xffffffffu, ulo));
                float rhi = __uint_as_float(__reduce_max_sync(0xffffffffu, uhi));
                if (lane == 0)
                    *(float2*)(op + h * 64 + 2 * t) = make_float2(rlo, rhi);
            }
        }
    }
}

// ---------------------------------------------------------------------------
extern "C" void kernel_launch(void* const* d_in, const int* in_sizes, int n_in,
                              void* d_out, int out_size)
{
    const float* xyzs  = (const float*)d_in[0];
    const float* feats = (const float*)d_in[1];
    const float* w1 = (const float*)d_in[2];
    const float* b1 = (const float*)d_in[3];
    const float* g1 = (const float*)d_in[4];
    const float* bt1= (const float*)d_in[5];
    const float* m1 = (const float*)d_in[6];
    const float* v1 = (const float*)d_in[7];
    const float* w2 = (const float*)d_in[8];
    const float* b2 = (const float*)d_in[9];
    const float* g2 = (const float*)d_in[10];
    const float* bt2= (const float*)d_in[11];
    const float* m2 = (const float*)d_in[12];
    const float* v2 = (const float*)d_in[13];
    const float* w3 = (const float*)d_in[14];
    const float* b3 = (const float*)d_in[15];
    const float* g3 = (const float*)d_in[16];
    const float* bt3= (const float*)d_in[17];
    const float* m3 = (const float*)d_in[18];
    const float* v3 = (const float*)d_in[19];

    float* outc = (float*)d_out;                      // [B,S,3]
    float* outf = outc + (size_t)B_ * S_ * 3;         // [B,S,128]

    // FPS uses 128 KB but requests 192 KB to keep worker CTAs off its 8 SMs.
    const int FPS_SMEM  = 192 * 1024;
    const int BALL_SMEM = N_ * sizeof(float4);                    // 128 KB
    const int MLP_SMEM  = (CIN_ * 64 + 64 * 64 + 64 * 128 + 64 + 64 + 128 + 256
                           + 128 * XS) * sizeof(float);           // ~104 KB

    // geometric taper (ratio ~0.9, multiples of 16, sum = 2048)
    static const int CB[CH + 1] =
        {0, 320, 608, 864, 1088, 1296, 1488, 1648, 1792, 1920, 2048};

    static cudaStream_t ws = nullptr;
    static cudaEvent_t  evF[CH];
    static cudaEvent_t  evJ;
    if (!ws) {
        cudaStreamCreateWithFlags(&ws, cudaStreamNonBlocking);
        for (int k = 0; k < CH; k++)
            cudaEventCreateWithFlags(&evF[k], cudaEventDisableTiming);
        cudaEventCreateWithFlags(&evJ, cudaEventDisableTiming);
        cudaFuncSetAttribute(fps_kernel,  cudaFuncAttributeMaxDynamicSharedMemorySize, FPS_SMEM);
        cudaFuncSetAttribute(ball_kernel, cudaFuncAttributeMaxDynamicSharedMemorySize, BALL_SMEM);
        cudaFuncSetAttribute(mlp_kernel,  cudaFuncAttributeMaxDynamicSharedMemorySize, MLP_SMEM);
    }

    for (int k = 0; k < CH; k++) {
        const int c0 = CB[k], c1 = CB[k + 1];
        const int sz = c1 - c0;
        fps_kernel<<<B_, FTH, FPS_SMEM>>>(xyzs, outc,
                                          (k == 0) ? 1 : c0, c1,
                                          (k == 0) ? 1 : 0);
        cudaEventRecord(evF[k], 0);
        cudaStreamWaitEvent(ws, evF[k], 0);
        ball_kernel<<<B_ * (sz / 16), 512, BALL_SMEM, ws>>>(xyzs, outc, c0);
        mlp_kernel <<<B_ * (sz / (WPB * CPW)), 128, MLP_SMEM, ws>>>(
            xyzs, feats,
            w1, b1, g1, bt1, m1, v1,
            w2, b2, g2, bt2, m2, v2,
            w3, b3, g3, bt3, m3, v3,
            outc, outf, c0);
    }
    cudaEventRecord(evJ, ws);
    cudaStreamWaitEvent(0, evJ, 0);
}

// round 16
// speedup vs baseline: 1.1316x; 1.1316x over previous
#include <cuda_runtime.h>
#include <cstdint>
#include <cstddef>

#define B_   8
#define N_   8192
#define S_   2048
#define K_   32
#define F_   64
#define CIN_ 67
#define EPSF 1e-5f

#define CH   8           // uniform pipeline chunks (tapers regressed twice)
#define CS   (S_ / CH)   // 256 centers per batch per chunk

#define FTH  256         // FPS threads per CTA
#define NP   16          // packed pairs per thread (32 points)

typedef unsigned long long ull;

// scratch
__device__ int   g_gidx[B_ * S_ * K_];
__device__ float g_mind[B_][N_];

// ---- packed f32x2 helpers (per-lane IEEE rn, bit-identical to scalar) ----
__device__ __forceinline__ ull pk2(float lo, float hi) {
    ull r; asm("mov.b64 %0, {%1, %2};" : "=l"(r) : "f"(lo), "f"(hi)); return r;
}
__device__ __forceinline__ void upk2(ull v, float& lo, float& hi) {
    asm("mov.b64 {%0, %1}, %2;" : "=f"(lo), "=f"(hi) : "l"(v));
}
__device__ __forceinline__ ull add2(ull a, ull b) {
    ull r; asm("add.rn.f32x2 %0, %1, %2;" : "=l"(r) : "l"(a), "l"(b)); return r;
}
__device__ __forceinline__ ull mul2(ull a, ull b) {
    ull r; asm("mul.rn.f32x2 %0, %1, %2;" : "=l"(r) : "l"(a), "l"(b)); return r;
}
__device__ __forceinline__ ull fma2(ull a, ull b, ull c) {
    ull r; asm("fma.rn.f32x2 %0, %1, %2, %3;" : "=l"(r) : "l"(a), "l"(b), "l"(c)); return r;
}

// ---------------------------------------------------------------------------
// Kernel 1: FPS chunk [s0, s1). One CTA per batch, 256 threads, 32 pts/thread
// (16 packed pairs, register-resident). Points stored in smem as float4 so
// the per-step center fetch is ONE LDS.128 (validated -14%/step).
// mind persisted between chunks. Distance: per-lane rn ops in canonical order
// ((dx*dx+dy*dy)+dz*dz). One barrier per step; exact argmax tie-break.
// ---------------------------------------------------------------------------
__global__ __launch_bounds__(FTH, 1)
void fps_kernel(const float* __restrict__ xyzs, float* __restrict__ outc,
                int s0, int s1, int first)
{
    extern __shared__ float4 spt[];     // [N_] x,y,z,-
    __shared__ ull swp[2][32];

    const int b    = blockIdx.x;
    const int tid  = threadIdx.x;
    const int lane = tid & 31;
    const int wid  = tid >> 5;          // 0..7
    const float* xyz = xyzs + (size_t)b * N_ * 3;

    // neutral keys for unused warp slots 8..31 (dist bits 0, idx ~0)
    if (tid < 32 && tid >= 8) {
        swp[0][tid] = 0xffffffffull;
        swp[1][tid] = 0xffffffffull;
    }

    ull px2[NP], py2[NP], pz2[NP];
    float mind[2 * NP];
#pragma unroll
    for (int p = 0; p < NP; p++) {
        int i0 = tid + (2 * p) * FTH;
        int i1 = tid + (2 * p + 1) * FTH;
        float X0 = xyz[i0 * 3 + 0], Y0 = xyz[i0 * 3 + 1], Z0 = xyz[i0 * 3 + 2];
        float X1 = xyz[i1 * 3 + 0], Y1 = xyz[i1 * 3 + 1], Z1 = xyz[i1 * 3 + 2];
        px2[p] = pk2(X0, X1); py2[p] = pk2(Y0, Y1); pz2[p] = pk2(Z0, Z1);
        spt[i0] = make_float4(X0, Y0, Z0, 0.0f);
        spt[i1] = make_float4(X1, Y1, Z1, 0.0f);
        if (first) {
            mind[2 * p] = 1e10f; mind[2 * p + 1] = 1e10f;
        } else {
            mind[2 * p]     = g_mind[b][i0];
            mind[2 * p + 1] = g_mind[b][i1];
        }
    }
    __syncthreads();

    float cx, cy, cz;
    if (first) {
        float4 p0 = spt[0];
        cx = p0.x; cy = p0.y; cz = p0.z;
        if (tid == 0) {
            float* o = outc + (size_t)b * S_ * 3;
            o[0] = cx; o[1] = cy; o[2] = cz;
        }
    } else {
        const float* o = outc + ((size_t)b * S_ + (s0 - 1)) * 3;
        cx = o[0]; cy = o[1]; cz = o[2];
    }

    for (int s = s0; s < s1; s++) {
        ull ncx2 = pk2(-cx, -cx), ncy2 = pk2(-cy, -cy), ncz2 = pk2(-cz, -cz);

        float bv = -1.0f;
#pragma unroll
        for (int p = 0; p < NP; p++) {
            ull dx2 = add2(px2[p], ncx2);
            ull dy2 = add2(py2[p], ncy2);
            ull dz2 = add2(pz2[p], ncz2);
            ull d2  = add2(add2(mul2(dx2, dx2), mul2(dy2, dy2)), mul2(dz2, dz2));
            float dlo, dhi; upk2(d2, dlo, dhi);
            float m0 = fminf(mind[2 * p],     dlo);
            float m1 = fminf(mind[2 * p + 1], dhi);
            mind[2 * p]     = m0;
            mind[2 * p + 1] = m1;
            bv = fmaxf(bv, fmaxf(m0, m1));
        }
        // distances >= 0 -> float order == unsigned bit order
        unsigned wmax  = __reduce_max_sync(0xffffffffu, __float_as_uint(bv));
        float    wmaxf = __uint_as_float(wmax);
        unsigned cand  = 0xffffffffu;
        if (__float_as_uint(bv) == wmax) {   // only holders scan
#pragma unroll
            for (int j = 2 * NP - 1; j >= 0; j--)
                if (mind[j] == wmaxf) cand = (unsigned)(tid + j * FTH);
        }
        cand = __reduce_min_sync(0xffffffffu, cand);
        if (lane == 0) swp[s & 1][wid] = ((ull)wmax << 32) | (ull)cand;
        __syncthreads();

        ull key = swp[s & 1][lane];
        unsigned hi = (unsigned)(key >> 32), lo = (unsigned)key;
        unsigned ghi  = __reduce_max_sync(0xffffffffu, hi);
        unsigned gidx = __reduce_min_sync(0xffffffffu, (hi == ghi) ? lo : 0xffffffffu);

        float4 cp = spt[gidx];          // one LDS.128
        cx = cp.x; cy = cp.y; cz = cp.z;
        if (tid == 0) {
            float* o = outc + ((size_t)b * S_ + s) * 3;
            o[0] = cx; o[1] = cy; o[2] = cz;
        }
    }

    // persist mind for the next chunk
#pragma unroll
    for (int p = 0; p < NP; p++) {
        g_mind[b][tid + (2 * p) * FTH]     = mind[2 * p];
        g_mind[b][tid + (2 * p + 1) * FTH] = mind[2 * p + 1];
    }
}

// ---------------------------------------------------------------------------
// Kernel 2: ball query chunk, warp-per-center ballot scan (R10/R14 config).
// ---------------------------------------------------------------------------
__global__ __launch_bounds__(512)
void ball_kernel(const float* __restrict__ xyzs, const float* __restrict__ centers,
                 int s0)
{
    extern __shared__ float4 sp[];   // [N_] : 128 KB

    const int bpb  = CS / 16;               // blocks per batch
    const int b    = blockIdx.x / bpb;
    const int soff = (blockIdx.x % bpb) * 16;
    const float* xyz = xyzs + (size_t)b * N_ * 3;

    for (int i = threadIdx.x; i < N_; i += 512) {
        float X = xyz[i * 3 + 0];
        float Y = xyz[i * 3 + 1];
        float Z = xyz[i * 3 + 2];
        float nrm = __fadd_rn(__fadd_rn(__fmul_rn(X, X), __fmul_rn(Y, Y)),
                              __fmul_rn(Z, Z));
        sp[i] = make_float4(X, Y, Z, nrm);
    }
    __syncthreads();

    const int warp = threadIdx.x >> 5;
    const int lane = threadIdx.x & 31;
    const int ci   = b * S_ + s0 + soff + warp;
    const float* c = centers + (size_t)ci * 3;
    const float cx = c[0], cy = c[1], cz = c[2];
    const float cc = __fadd_rn(__fadd_rn(__fmul_rn(cx, cx), __fmul_rn(cy, cy)),
                               __fmul_rn(cz, cz));
    const float R2 = 0.2f * 0.2f;
    const unsigned below = (1u << lane) - 1u;

    int cnt = 0;
    for (int chunk = 0; chunk < N_ / 32; chunk++) {
        int n = chunk * 32 + lane;
        float4 p = sp[n];
        float dot = __fadd_rn(__fadd_rn(__fmul_rn(cx, p.x), __fmul_rn(cy, p.y)),
                              __fmul_rn(cz, p.z));
        float d2  = __fsub_rn(__fadd_rn(cc, p.w), __fmul_rn(2.0f, dot));
        bool hit = (d2 <= R2);
        unsigned m = __ballot_sync(0xffffffffu, hit);
        int pos = cnt + __popc(m & below);
        if (hit && pos < K_) g_gidx[(size_t)ci * K_ + pos] = n;
        cnt += __popc(m);
        if (cnt >= K_) break;
    }
    for (int t = cnt + lane; t < K_; t += 32) g_gidx[(size_t)ci * K_ + t] = -1;
}

// ---------------------------------------------------------------------------
// Kernel 3: gather + 3-layer MLP (BN folded) + max over K, chunked (R14 form).
// ---------------------------------------------------------------------------
#define WPB 4
#define CPW 2
#define XS  69   // staging row stride (67 used), odd -> conflict-free

__device__ __forceinline__ void step64(ull* __restrict__ acc, float xv,
                                       const float* __restrict__ wrow)
{
    ull xv2 = pk2(xv, xv);
    const ulonglong2* wp = (const ulonglong2*)wrow;
#pragma unroll
    for (int t = 0; t < 16; t++) {
        ulonglong2 w = wp[t];
        acc[2 * t]     = fma2(xv2, w.x, acc[2 * t]);
        acc[2 * t + 1] = fma2(xv2, w.y, acc[2 * t + 1]);
    }
}

__global__ __launch_bounds__(128, 2)
void mlp_kernel(const float* __restrict__ xyzs, const float* __restrict__ feats,
                const float* __restrict__ w1, const float* __restrict__ b1,
                const float* __restrict__ g1, const float* __restrict__ bt1,
                const float* __restrict__ m1, const float* __restrict__ v1,
                const float* __restrict__ w2, const float* __restrict__ b2,
                const float* __restrict__ g2, const float* __restrict__ bt2,
                const float* __restrict__ m2, const float* __restrict__ v2,
                const float* __restrict__ w3, const float* __restrict__ b3,
                const float* __restrict__ g3, const float* __restrict__ bt3,
                const float* __restrict__ m3, const float* __restrict__ v3,
                const float* __restrict__ centers, float* __restrict__ outf,
                int s0)
{
    extern __shared__ float sm3[];
    float* sW1 = sm3;
    float* sW2 = sW1 + CIN_ * 64;
    float* sW3 = sW2 + 64 * 64;
    float* sB1 = sW3 + 64 * 128;
    float* sB2 = sB1 + 64;
    float* sB3 = sB2 + 64;
    float* sS  = sB3 + 128;
    float* sX  = sS + 256;

    const int tid = threadIdx.x;

    if (tid < 64) {
        float s = g1[tid] * rsqrtf(v1[tid] + EPSF);
        sS[tid] = s;
        sB1[tid] = (b1[tid] - m1[tid]) * s + bt1[tid];
    } else {
        int o = tid - 64;
        float s = g2[o] * rsqrtf(v2[o] + EPSF);
        sS[64 + o] = s;
        sB2[o] = (b2[o] - m2[o]) * s + bt2[o];
    }
    {
        float s = g3[tid] * rsqrtf(v3[tid] + EPSF);
        sS[128 + tid] = s;
        sB3[tid] = (b3[tid] - m3[tid]) * s + bt3[tid];
    }
    __syncthreads();

    for (int i = tid; i < CIN_ * 64; i += 128) {
        int c = i >> 6, o = i & 63;
        sW1[i] = w1[o * CIN_ + c] * sS[o];
    }
    for (int i = tid; i < 64 * 64; i += 128) {
        int c = i >> 6, o = i & 63;
        sW2[i] = w2[o * 64 + c] * sS[64 + o];
    }
    for (int i = tid; i < 64 * 128; i += 128) {
        int c = i >> 7, o = i & 127;
        sW3[i] = w3[o * 64 + c] * sS[128 + o];
    }
    __syncthreads();

    const int warp = tid >> 5;
    const int lane = tid & 31;
    float* myX = sX + tid * XS;

    const int pbb = CS / (WPB * CPW);             // blocks per batch
    const int b   = blockIdx.x / pbb;
    const int cb  = b * S_ + s0 + (blockIdx.x % pbb) * (WPB * CPW);

    for (int it = 0; it < CPW; it++) {
        const int ci = cb + warp * CPW + it;

        const int  ig    = g_gidx[(size_t)ci * K_ + lane];
        const bool valid = (ig >= 0);
        const int  ip    = valid ? ig : 0;
        const float* ctr = centers + (size_t)ci * 3;
        const float* p   = xyzs + ((size_t)b * N_ + ip) * 3;
        myX[0] = valid ? (p[0] - ctr[0]) : 0.0f;
        myX[1] = valid ? (p[1] - ctr[1]) : 0.0f;
        myX[2] = valid ? (p[2] - ctr[2]) : 0.0f;
        const float4* f4 = (const float4*)(feats + ((size_t)b * N_ + ip) * F_);
#pragma unroll
        for (int q = 0; q < 16; q++) {
            float4 t = f4[q];
            myX[3 + 4 * q + 0] = valid ? t.x : 0.0f;
            myX[3 + 4 * q + 1] = valid ? t.y : 0.0f;
            myX[3 + 4 * q + 2] = valid ? t.z : 0.0f;
            myX[3 + 4 * q + 3] = valid ? t.w : 0.0f;
        }

        ull acc[32];

        // ---- layer 1: 67 -> 64 ----
#pragma unroll
        for (int t = 0; t < 32; t++) acc[t] = ((const ull*)sB1)[t];
#pragma unroll 1
        for (int c = 0; c < CIN_; c++) step64(acc, myX[c], sW1 + c * 64);
#pragma unroll
        for (int t = 0; t < 32; t++) {
            float lo, hi; upk2(acc[t], lo, hi);
            myX[2 * t]     = fmaxf(lo, 0.0f);
            myX[2 * t + 1] = fmaxf(hi, 0.0f);
        }

        // ---- layer 2: 64 -> 64 ----
#pragma unroll
        for (int t = 0; t < 32; t++) acc[t] = ((const ull*)sB2)[t];
#pragma unroll 1
        for (int c = 0; c < 64; c++) step64(acc, myX[c], sW2 + c * 64);
#pragma unroll
        for (int t = 0; t < 32; t++) {
            float lo, hi; upk2(acc[t], lo, hi);
            myX[2 * t]     = fmaxf(lo, 0.0f);
            myX[2 * t + 1] = fmaxf(hi, 0.0f);
        }

        // ---- layer 3: 64 -> 128 in two halves, relu, warp max over K ----
        float* op = outf + (size_t)ci * 128;
#pragma unroll 1
        for (int h = 0; h < 2; h++) {
#pragma unroll
            for (int t = 0; t < 32; t++) acc[t] = ((const ull*)(sB3 + h * 64))[t];
#pragma unroll 1
            for (int c = 0; c < 64; c++) step64(acc, myX[c], sW3 + c * 128 + h * 64);
#pragma unroll
            for (int t = 0; t < 32; t++) {
                float lo, hi; upk2(acc[t], lo, hi);
                unsigned ulo = __float_as_uint(fmaxf(lo, 0.0f)) & 0x7fffffffu;
                unsigned uhi = __float_as_uint(fmaxf(hi, 0.0f)) & 0x7fffffffu;
                float rlo = __uint_as_float(__reduce_max_sync(0xffffffffu, ulo));
                float rhi = __uint_as_float(__reduce_max_sync(0xffffffffu, uhi));
                if (lane == 0)
                    *(float2*)(op + h * 64 + 2 * t) = make_float2(rlo, rhi);
            }
        }
    }
}

// ---------------------------------------------------------------------------
extern "C" void kernel_launch(void* const* d_in, const int* in_sizes, int n_in,
                              void* d_out, int out_size)
{
    const float* xyzs  = (const float*)d_in[0];
    const float* feats = (const float*)d_in[1];
    const float* w1 = (const float*)d_in[2];
    const float* b1 = (const float*)d_in[3];
    const float* g1 = (const float*)d_in[4];
    const float* bt1= (const float*)d_in[5];
    const float* m1 = (const float*)d_in[6];
    const float* v1 = (const float*)d_in[7];
    const float* w2 = (const float*)d_in[8];
    const float* b2 = (const float*)d_in[9];
    const float* g2 = (const float*)d_in[10];
    const float* bt2= (const float*)d_in[11];
    const float* m2 = (const float*)d_in[12];
    const float* v2 = (const float*)d_in[13];
    const float* w3 = (const float*)d_in[14];
    const float* b3 = (const float*)d_in[15];
    const float* g3 = (const float*)d_in[16];
    const float* bt3= (const float*)d_in[17];
    const float* m3 = (const float*)d_in[18];
    const float* v3 = (const float*)d_in[19];

    float* outc = (float*)d_out;                      // [B,S,3]
    float* outf = outc + (size_t)B_ * S_ * 3;         // [B,S,128]

    // FPS uses 128 KB but requests 192 KB to keep worker CTAs off its 8 SMs.
    const int FPS_SMEM  = 192 * 1024;
    const int BALL_SMEM = N_ * sizeof(float4);                    // 128 KB
    const int MLP_SMEM  = (CIN_ * 64 + 64 * 64 + 64 * 128 + 64 + 64 + 128 + 256
                           + 128 * XS) * sizeof(float);           // ~104 KB

    static cudaStream_t ws = nullptr;
    static cudaEvent_t  evF[CH];
    static cudaEvent_t  evJ;
    if (!ws) {
        cudaStreamCreateWithFlags(&ws, cudaStreamNonBlocking);
        for (int k = 0; k < CH; k++)
            cudaEventCreateWithFlags(&evF[k], cudaEventDisableTiming);
        cudaEventCreateWithFlags(&evJ, cudaEventDisableTiming);
        cudaFuncSetAttribute(fps_kernel,  cudaFuncAttributeMaxDynamicSharedMemorySize, FPS_SMEM);
        cudaFuncSetAttribute(ball_kernel, cudaFuncAttributeMaxDynamicSharedMemorySize, BALL_SMEM);
        cudaFuncSetAttribute(mlp_kernel,  cudaFuncAttributeMaxDynamicSharedMemorySize, MLP_SMEM);
    }

    for (int k = 0; k < CH; k++) {
        fps_kernel<<<B_, FTH, FPS_SMEM>>>(xyzs, outc,
                                          (k == 0) ? 1 : k * CS, (k + 1) * CS,
                                          (k == 0) ? 1 : 0);
        cudaEventRecord(evF[k], 0);
        cudaStreamWaitEvent(ws, evF[k], 0);
        ball_kernel<<<B_ * (CS / 16), 512, BALL_SMEM, ws>>>(xyzs, outc, k * CS);
        mlp_kernel <<<B_ * (CS / (WPB * CPW)), 128, MLP_SMEM, ws>>>(
            xyzs, feats,
            w1, b1, g1, bt1, m1, v1,
            w2, b2, g2, bt2, m2, v2,
            w3, b3, g3, bt3, m3, v3,
            outc, outf, k * CS);
    }
    cudaEventRecord(evJ, ws);
    cudaStreamWaitEvent(0, evJ, 0);
}